// round 4
// baseline (speedup 1.0000x reference)
#include <cuda_runtime.h>

// ---------------------------------------------------------------------------
// NCF_Feature fully fused: bag + one-hot + GEMVs + grid-sync batchnorm + MLP
// in ONE persistent kernel (256 CTAs, all co-resident at 2 CTA/SM:
// 201KB smem/SM <= 228KB, 64 regs, 32 warps -> wave-1 guaranteed).
// ---------------------------------------------------------------------------

#define B_ROWS 16384
#define TAGS   4096
#define GMAIN  256            // blocks; 64 rows per block
#define NWARP  16             // warps per block (512 threads)

// Global scratch + sync state (allocation-free rule: __device__ globals)
__device__ float g_part[GMAIN * 40];            // per-block: sum[20], sumsq[20]
__device__ float g_scale[20];
__device__ float g_shift[20];
__device__ unsigned int g_arrive;               // zero-initialized
__device__ unsigned int g_release;
__device__ unsigned int g_done;

__device__ __forceinline__ float warpsum(float v) {
#pragma unroll
    for (int o = 16; o; o >>= 1) v += __shfl_xor_sync(0xffffffffu, v, o);
    return v;
}

// Shared memory layout (floats):
//  sE    [0 .. 20480)          E_item_tag SoA (phase 1); reused phase 2 for
//        pW1 (64x31), pb1, pW2 (32x65), pb2, pW3, h1s (16 warps x 64)
//  sWu   [20480 .. 21760)
//  sWi   [21760 .. 23040)
//  sRed  [23040 .. 23680)      16*40 warp BN partials; reused for stats reduce
//  sFeat [23680 .. 25728)      64 rows * 32 cols
#define SM_TOTALF 25728

__global__ void __launch_bounds__(512, 2)
k_fused(const float* __restrict__ uf_g, const float* __restrict__ if_g,
        const float* __restrict__ ut_g, const float* __restrict__ it_g,
        const float* __restrict__ Wu,   const float* __restrict__ bu,
        const float* __restrict__ Wi,   const float* __restrict__ bi,
        const float* __restrict__ Eu,   const float* __restrict__ Ei,
        const float* __restrict__ g1,   const float* __restrict__ be1,
        const float* __restrict__ g2,   const float* __restrict__ be2,
        const float* __restrict__ W1,   const float* __restrict__ b1,
        const float* __restrict__ W2,   const float* __restrict__ b2,
        const float* __restrict__ W3,   const float* __restrict__ b3,
        float* __restrict__ out)
{
    extern __shared__ float sm[];
    float* sE    = sm;
    float* sWu   = sm + 20480;
    float* sWi   = sm + 21760;
    float* sRed  = sm + 23040;
    float* sFeat = sm + 23680;
    __shared__ int sIsLast;

    const int tid = threadIdx.x;

    // ---- stage E_item_tag [4096,5] -> SoA shared ----
    for (int i = tid; i < TAGS; i += 512) {
        float e0 = Ei[i * 5 + 0], e1 = Ei[i * 5 + 1], e2 = Ei[i * 5 + 2];
        float e3 = Ei[i * 5 + 3], e4 = Ei[i * 5 + 4];
        sE[0 * TAGS + i] = e0; sE[1 * TAGS + i] = e1; sE[2 * TAGS + i] = e2;
        sE[3 * TAGS + i] = e3; sE[4 * TAGS + i] = e4;
    }
    for (int i = tid; i < 1280; i += 512) { sWu[i] = Wu[i]; sWi[i] = Wi[i]; }
    __syncthreads();

    const int warp = tid >> 5, lane = tid & 31;
    const int rowloc0 = warp * 4;                    // 4 rows per warp (block-local)
    const int rowglb0 = blockIdx.x * 64 + rowloc0;
    const float4* sE4  = (const float4*)sE;
    const float4* sWu4 = (const float4*)sWu;
    const float4* sWi4 = (const float4*)sWi;

    float su = 0.f, sq = 0.f;

    // ================= PHASE 1: stream =================
#pragma unroll 1
    for (int q = 0; q < 2; q++) {
        const int rl0 = rowloc0 + q * 2;
        const int rg0 = rowglb0 + q * 2;

        // ---- weighted tag bag (2 rows, software-pipelined: 4 LDG in flight) ----
        const float4* t0 = (const float4*)(ut_g + (size_t)(rg0 + 0) * TAGS);
        const float4* t1 = (const float4*)(ut_g + (size_t)(rg0 + 1) * TAGS);
        float acc[2][5];
#pragma unroll
        for (int r = 0; r < 2; r++)
#pragma unroll
            for (int k = 0; k < 5; k++) acc[r][k] = 0.f;

        float4 n0 = t0[lane], n1 = t1[lane];
#pragma unroll 1
        for (int i = lane; i < TAGS / 4; i += 32) {
            float4 c0 = n0, c1 = n1;
            if (i + 32 < TAGS / 4) { n0 = t0[i + 32]; n1 = t1[i + 32]; }
            float4 ee[5];
#pragma unroll
            for (int k = 0; k < 5; k++) ee[k] = sE4[k * (TAGS / 4) + i];
#pragma unroll
            for (int k = 0; k < 5; k++) {
                acc[0][k] += c0.x * ee[k].x + c0.y * ee[k].y + c0.z * ee[k].z + c0.w * ee[k].w;
                acc[1][k] += c1.x * ee[k].x + c1.y * ee[k].y + c1.z * ee[k].z + c1.w * ee[k].w;
            }
        }
#pragma unroll
        for (int r = 0; r < 2; r++) {
#pragma unroll
            for (int k = 0; k < 5; k++) {
                float s = warpsum(acc[r][k]) * 0.1f;
                if (lane == k) sFeat[(rl0 + r) * 32 + 10 + k] = s;
            }
        }

        // ---- per-row: GEMVs + one-hot search (chunk0 preloaded, ping-pong) ----
#pragma unroll 1
        for (int r = 0; r < 2; r++) {
            const int rl = rl0 + r, rg = rg0 + r;
            const float4* it4 = (const float4*)(it_g + (size_t)rg * TAGS);

            // preload search chunk 0 (latency hidden behind GEMV)
            float4 va[4];
#pragma unroll
            for (int k = 0; k < 4; k++) va[k] = it4[k * 32 + lane];

            float4 xu = ((const float4*)(uf_g + (size_t)rg * 128))[lane];
            float4 xi = ((const float4*)(if_g + (size_t)rg * 128))[lane];
#pragma unroll
            for (int j = 0; j < 10; j++) {
                float4 wu = sWu4[j * 32 + lane];
                float s = warpsum(xu.x * wu.x + xu.y * wu.y + xu.z * wu.z + xu.w * wu.w) + bu[j];
                if (lane == j) { sFeat[rl * 32 + j] = s; su += s; sq += s * s; }
                float4 wi = sWi4[j * 32 + lane];
                float s2 = warpsum(xi.x * wi.x + xi.y * wi.y + xi.z * wi.z + xi.w * wi.w) + bi[j];
                if (lane == j + 10) { sFeat[rl * 32 + 15 + j] = s2; su += s2; sq += s2 * s2; }
            }

            // search: 512-col chunks, double-buffered (next chunk's loads issued
            // before current chunk's ballot)
            int hot = 0;
            bool found = false;
            float4 vb[4];
#pragma unroll 1
            for (int base = 0; base < 1024 && !found; base += 256) {
                if (base + 128 < 1024) {
#pragma unroll
                    for (int k = 0; k < 4; k++) vb[k] = it4[base + 128 + k * 32 + lane];
                }
                int m = 0;
#pragma unroll
                for (int k = 0; k < 4; k++) {
                    m |= (va[k].x == 1.f) << (k * 4 + 0);
                    m |= (va[k].y == 1.f) << (k * 4 + 1);
                    m |= (va[k].z == 1.f) << (k * 4 + 2);
                    m |= (va[k].w == 1.f) << (k * 4 + 3);
                }
                unsigned bal = __ballot_sync(0xffffffffu, m != 0);
                if (bal) {
                    int src = __ffs(bal) - 1;
                    int mm  = __shfl_sync(0xffffffffu, m, src);
                    int bit = __ffs(mm) - 1;
                    hot = 4 * (base + (bit >> 2) * 32 + src) + (bit & 3);
                    found = true; break;
                }
                if (base + 128 < 1024) {
                    if (base + 256 < 1024) {
#pragma unroll
                        for (int k = 0; k < 4; k++) va[k] = it4[base + 256 + k * 32 + lane];
                    }
                    m = 0;
#pragma unroll
                    for (int k = 0; k < 4; k++) {
                        m |= (vb[k].x == 1.f) << (k * 4 + 0);
                        m |= (vb[k].y == 1.f) << (k * 4 + 1);
                        m |= (vb[k].z == 1.f) << (k * 4 + 2);
                        m |= (vb[k].w == 1.f) << (k * 4 + 3);
                    }
                    bal = __ballot_sync(0xffffffffu, m != 0);
                    if (bal) {
                        int src = __ffs(bal) - 1;
                        int mm  = __shfl_sync(0xffffffffu, m, src);
                        int bit = __ffs(mm) - 1;
                        hot = 4 * (base + 128 + (bit >> 2) * 32 + src) + (bit & 3);
                        found = true; break;
                    }
                }
            }
            if (lane < 5) sFeat[rl * 32 + 25 + lane] = Eu[(size_t)hot * 5 + lane];
        }
    }

    // ---- per-block BN partials -> g_part ----
    if (lane < 20) { sRed[warp * 40 + lane] = su; sRed[warp * 40 + 20 + lane] = sq; }
    __syncthreads();
    if (tid < 40) {
        float s = 0.f;
#pragma unroll
        for (int w = 0; w < NWARP; w++) s += sRed[w * 40 + tid];
        g_part[blockIdx.x * 40 + tid] = s;
    }

    // ================= GRID BARRIER (all 256 CTAs wave-1 co-resident) ========
    __threadfence();
    __syncthreads();
    if (tid == 0) {
        unsigned old = atomicAdd(&g_arrive, 1u);
        sIsLast = (old == GMAIN - 1) ? 1 : 0;
    }
    __syncthreads();

    // load MLP weights into sE (overlaps other blocks' stragglers)
    float* pW1 = sE;            // 64 x stride 31
    float* pb1 = sE + 1984;
    float* pW2 = sE + 2048;     // 32 x stride 65
    float* pb2 = sE + 4128;
    float* pW3 = sE + 4160;
    float* h1s = sE + 4300;     // 16 warps x 64
    for (int i = tid; i < 1920; i += 512) pW1[(i / 30) * 31 + (i % 30)] = W1[i];
    for (int i = tid; i < 2048; i += 512) pW2[(i / 64) * 65 + (i % 64)] = W2[i];
    if (tid < 64) pb1[tid] = b1[tid];
    if (tid < 32) { pb2[tid] = b2[tid]; pW3[tid] = W3[tid]; }

    if (sIsLast) {
        // stats reduce: 8 groups x 40, each over 32 blocks (deterministic)
        const int j = tid % 40, g = tid / 40;
        float s = 0.f;
        if (tid < 320) {
#pragma unroll 4
            for (int i = 0; i < 32; i++) s += g_part[(g * 32 + i) * 40 + j];
            sRed[g * 40 + j] = s;
        }
        __syncthreads();
        if (tid < 20) {
            float s0 = 0.f, s1 = 0.f;
#pragma unroll
            for (int gg = 0; gg < 8; gg++) { s0 += sRed[gg * 40 + tid]; s1 += sRed[gg * 40 + 20 + tid]; }
            float mean = s0 * (1.f / B_ROWS);
            float var  = s1 * (1.f / B_ROWS) - mean * mean;
            float ga = (tid < 10) ? g1[tid]  : g2[tid - 10];
            float be = (tid < 10) ? be1[tid] : be2[tid - 10];
            float sc = ga * rsqrtf(var + 1e-5f);
            g_scale[tid] = sc;
            g_shift[tid] = be - mean * sc;
        }
        __threadfence();
        __syncthreads();
        if (tid == 0) atomicExch(&g_release, 1u);
    }

    if (tid == 0) {
        while (atomicAdd(&g_release, 0u) == 0u) __nanosleep(64);
    }
    __syncthreads();
    __threadfence();

    // ================= PHASE 2: batchnorm + MLP =================
    // normalize feat tile in place: cols 0..9 use stats 0..9; 15..24 use 10..19
    for (int i = tid; i < 64 * 20; i += 512) {
        int row = i / 20, j = i % 20;
        int col = (j < 10) ? j : (j + 5);
        sFeat[row * 32 + col] = sFeat[row * 32 + col] * g_scale[j] + g_shift[j];
    }
    __syncthreads();

    const float b3v = b3[0];
    float* h1w = h1s + warp * 64;
#pragma unroll 1
    for (int rr = 0; rr < 4; rr++) {
        const int rl = rowloc0 + rr;
        const float* x = sFeat + rl * 32;
        float s0 = pb1[lane], s1 = pb1[lane + 32];
        const float* w0 = pW1 + lane * 31;
        const float* w1 = pW1 + (lane + 32) * 31;
#pragma unroll
        for (int i = 0; i < 30; i++) {
            float xv = x[i];
            s0 += w0[i] * xv;
            s1 += w1[i] * xv;
        }
        h1w[lane] = fmaxf(s0, 0.f);
        h1w[lane + 32] = fmaxf(s1, 0.f);
        __syncwarp();
        float s = pb2[lane];
        const float* w2 = pW2 + lane * 65;
#pragma unroll
        for (int i = 0; i < 64; i++) s += w2[i] * h1w[i];
        float h2 = fmaxf(s, 0.f);
        float v = warpsum(pW3[lane] * h2) + b3v;
        if (lane == 0) out[blockIdx.x * 64 + rl] = fmaxf(v, 0.f);
        __syncwarp();
    }

    // ---- reset sync state for next graph replay ----
    __syncthreads();
    if (tid == 0) {
        __threadfence();
        unsigned old = atomicAdd(&g_done, 1u);
        if (old == GMAIN - 1) {
            g_arrive = 0u; g_release = 0u; g_done = 0u;
            __threadfence();
        }
    }
}

// ===========================================================================
extern "C" void kernel_launch(void* const* d_in, const int* in_sizes, int n_in,
                              void* d_out, int out_size)
{
    (void)in_sizes; (void)n_in; (void)out_size;
    const float* user_feature = (const float*)d_in[2];
    const float* item_feature = (const float*)d_in[3];
    const float* user_tag     = (const float*)d_in[4];
    const float* item_tag     = (const float*)d_in[5];
    const float* W_user = (const float*)d_in[6];
    const float* b_user = (const float*)d_in[7];
    const float* W_item = (const float*)d_in[8];
    const float* b_item = (const float*)d_in[9];
    const float* E_user_tag = (const float*)d_in[10];
    const float* E_item_tag = (const float*)d_in[11];
    const float* g1  = (const float*)d_in[12];
    const float* be1 = (const float*)d_in[13];
    const float* g2  = (const float*)d_in[14];
    const float* be2 = (const float*)d_in[15];
    const float* W1 = (const float*)d_in[16];
    const float* b1 = (const float*)d_in[17];
    const float* W2 = (const float*)d_in[18];
    const float* b2 = (const float*)d_in[19];
    const float* W3 = (const float*)d_in[20];
    const float* b3 = (const float*)d_in[21];

    const int smem_bytes = SM_TOTALF * (int)sizeof(float);  // 102,912 B
    cudaFuncSetAttribute(k_fused, cudaFuncAttributeMaxDynamicSharedMemorySize, smem_bytes);

    k_fused<<<GMAIN, 512, smem_bytes>>>(user_feature, item_feature, user_tag, item_tag,
                                        W_user, b_user, W_item, b_item,
                                        E_user_tag, E_item_tag,
                                        g1, be1, g2, be2,
                                        W1, b1, W2, b2, W3, b3,
                                        (float*)d_out);
}

// round 5
// speedup vs baseline: 1.1151x; 1.1151x over previous
#include <cuda_runtime.h>

// ---------------------------------------------------------------------------
// NCF_Feature: split structure (best known) with deeper memory pipelines.
//  k_main: bag (2x-unrolled, 4 LDG in flight) + GEMVs + one-hot (8-LDG chunks)
//          + BN partials; LAST block computes scale/shift (no extra kernel).
//  k_mlp : normalize + 30->64->32->1 ReLU MLP.
// ---------------------------------------------------------------------------

#define B_ROWS 16384
#define TAGS   4096
#define GMAIN  256            // blocks; 64 rows per block
#define NWARP  16             // warps per block (512 threads)

// Scratch (allocation-free rule: __device__ globals)
__device__ float g_feat[(size_t)B_ROWS * 32];   // [B][32]: u(10) eut(5) i(10) eit(5) pad
__device__ float g_part[GMAIN * 40];            // per-block: sum[20], sumsq[20]
__device__ float g_scale[20];
__device__ float g_shift[20];
__device__ unsigned int g_arrive;               // zero-init; self-resetting

__device__ __forceinline__ float warpsum(float v) {
#pragma unroll
    for (int o = 16; o; o >>= 1) v += __shfl_xor_sync(0xffffffffu, v, o);
    return v;
}

// ===========================================================================
// Kernel 1: HBM streamer. 512 threads, 2 CTA/SM.
// ===========================================================================
__global__ void __launch_bounds__(512, 2)
k_main(const float* __restrict__ uf_g, const float* __restrict__ if_g,
       const float* __restrict__ ut_g, const float* __restrict__ it_g,
       const float* __restrict__ Wu,   const float* __restrict__ bu,
       const float* __restrict__ Wi,   const float* __restrict__ bi,
       const float* __restrict__ Eu,   const float* __restrict__ Ei,
       const float* __restrict__ g1,   const float* __restrict__ be1,
       const float* __restrict__ g2,   const float* __restrict__ be2)
{
    extern __shared__ float sm[];
    float* sE   = sm;                 // 5*4096 SoA
    float* sWu  = sm + 20480;         // 10*128
    float* sWi  = sm + 21760;         // 10*128
    float* sRed = sm + 23040;         // NWARP*40

    const int tid = threadIdx.x;

    // Stage E_item_tag [4096,5] -> SoA shared
    for (int i = tid; i < TAGS; i += 512) {
        float e0 = Ei[i * 5 + 0], e1 = Ei[i * 5 + 1], e2 = Ei[i * 5 + 2];
        float e3 = Ei[i * 5 + 3], e4 = Ei[i * 5 + 4];
        sE[0 * TAGS + i] = e0; sE[1 * TAGS + i] = e1; sE[2 * TAGS + i] = e2;
        sE[3 * TAGS + i] = e3; sE[4 * TAGS + i] = e4;
    }
    for (int i = tid; i < 1280; i += 512) { sWu[i] = Wu[i]; sWi[i] = Wi[i]; }
    __syncthreads();

    const int warp = tid >> 5, lane = tid & 31;
    const int rowbase = blockIdx.x * 64 + warp * 4;
    const float4* sE4  = (const float4*)sE;
    const float4* sWu4 = (const float4*)sWu;
    const float4* sWi4 = (const float4*)sWi;

    float su = 0.f, sq = 0.f;

#pragma unroll 1
    for (int q = 0; q < 2; q++) {
        const int r0 = rowbase + q * 2;

        // ---- weighted tag bag: 2 rows, 2x unrolled -> 4 LDG.128 in flight ----
        const float4* t0 = (const float4*)(ut_g + (size_t)(r0 + 0) * TAGS);
        const float4* t1 = (const float4*)(ut_g + (size_t)(r0 + 1) * TAGS);
        float acc0[5], acc1[5];
#pragma unroll
        for (int k = 0; k < 5; k++) { acc0[k] = 0.f; acc1[k] = 0.f; }

#pragma unroll 1
        for (int i = lane; i < TAGS / 4; i += 64) {
            // issue all 4 global loads before any use
            float4 a0 = t0[i];
            float4 a1 = t1[i];
            float4 b0 = t0[i + 32];
            float4 b1 = t1[i + 32];
            float4 ee;
#pragma unroll
            for (int k = 0; k < 5; k++) {
                ee = sE4[k * (TAGS / 4) + i];
                acc0[k] += a0.x * ee.x + a0.y * ee.y + a0.z * ee.z + a0.w * ee.w;
                acc1[k] += a1.x * ee.x + a1.y * ee.y + a1.z * ee.z + a1.w * ee.w;
            }
#pragma unroll
            for (int k = 0; k < 5; k++) {
                ee = sE4[k * (TAGS / 4) + i + 32];
                acc0[k] += b0.x * ee.x + b0.y * ee.y + b0.z * ee.z + b0.w * ee.w;
                acc1[k] += b1.x * ee.x + b1.y * ee.y + b1.z * ee.z + b1.w * ee.w;
            }
        }
#pragma unroll
        for (int k = 0; k < 5; k++) {
            float s0 = warpsum(acc0[k]) * 0.1f;
            float s1 = warpsum(acc1[k]) * 0.1f;
            if (lane == k) {
                g_feat[(size_t)(r0 + 0) * 32 + 10 + k] = s0;
                g_feat[(size_t)(r0 + 1) * 32 + 10 + k] = s1;
            }
        }

        // ---- per-row: GEMVs + one-hot search ----
#pragma unroll 1
        for (int r = 0; r < 2; r++) {
            const int rr = r0 + r;
            const float4* it4 = (const float4*)(it_g + (size_t)rr * TAGS);

            // hoist search chunk 0 (8 LDG.128) above the GEMVs: round 1 free
            float4 v[8];
#pragma unroll
            for (int k = 0; k < 8; k++) v[k] = it4[k * 32 + lane];

            float4 xu = ((const float4*)(uf_g + (size_t)rr * 128))[lane];
            float4 xi = ((const float4*)(if_g + (size_t)rr * 128))[lane];
#pragma unroll
            for (int j = 0; j < 10; j++) {
                float4 wu = sWu4[j * 32 + lane];
                float s = warpsum(xu.x * wu.x + xu.y * wu.y + xu.z * wu.z + xu.w * wu.w) + bu[j];
                if (lane == j) { g_feat[(size_t)rr * 32 + j] = s; su += s; sq += s * s; }
                float4 wi = sWi4[j * 32 + lane];
                float s2 = warpsum(xi.x * wi.x + xi.y * wi.y + xi.z * wi.z + xi.w * wi.w) + bi[j];
                if (lane == j + 10) { g_feat[(size_t)rr * 32 + 15 + j] = s2; su += s2; sq += s2 * s2; }
            }

            // search: 1024-col chunks (8 independent LDG.128 per round), early exit
            int hot = 0;
#pragma unroll 1
            for (int base = 0; base < 1024; base += 256) {
                int m = 0;
#pragma unroll
                for (int k = 0; k < 8; k++) {
                    m |= (v[k].x == 1.f) << (k * 4 + 0);
                    m |= (v[k].y == 1.f) << (k * 4 + 1);
                    m |= (v[k].z == 1.f) << (k * 4 + 2);
                    m |= (v[k].w == 1.f) << (k * 4 + 3);
                }
                unsigned bal = __ballot_sync(0xffffffffu, m != 0);
                if (bal) {
                    int src = __ffs(bal) - 1;
                    int mm  = __shfl_sync(0xffffffffu, m, src);
                    int bit = __ffs(mm) - 1;
                    hot = 4 * (base + (bit >> 2) * 32 + src) + (bit & 3);
                    break;
                }
                if (base + 256 < 1024) {
#pragma unroll
                    for (int k = 0; k < 8; k++) v[k] = it4[base + 256 + k * 32 + lane];
                }
            }
            if (lane < 5) g_feat[(size_t)rr * 32 + 25 + lane] = Eu[(size_t)hot * 5 + lane];
        }
    }

    // ---- per-block BN partials -> g_part ----
    if (lane < 20) { sRed[warp * 40 + lane] = su; sRed[warp * 40 + 20 + lane] = sq; }
    __syncthreads();
    if (tid < 40) {
        float s = 0.f;
#pragma unroll
        for (int w = 0; w < NWARP; w++) s += sRed[w * 40 + tid];
        g_part[blockIdx.x * 40 + tid] = s;
    }

    // ---- last-arriving block computes BN scale/shift (replaces k_stats) ----
    __threadfence();
    __syncthreads();
    __shared__ int sLast;
    if (tid == 0) sLast = (atomicAdd(&g_arrive, 1u) == GMAIN - 1);
    __syncthreads();
    if (sLast) {
        const int j = tid % 40, g = tid / 40;
        if (tid < 320) {
            float s = 0.f;
#pragma unroll 4
            for (int i = 0; i < 32; i++) s += g_part[(g * 32 + i) * 40 + j];
            sRed[g * 40 + j] = s;
        }
        __syncthreads();
        if (tid < 20) {
            float s0 = 0.f, s1 = 0.f;
#pragma unroll
            for (int gg = 0; gg < 8; gg++) { s0 += sRed[gg * 40 + tid]; s1 += sRed[gg * 40 + 20 + tid]; }
            float mean = s0 * (1.f / B_ROWS);
            float var  = s1 * (1.f / B_ROWS) - mean * mean;   // biased
            float ga = (tid < 10) ? g1[tid]  : g2[tid - 10];
            float be = (tid < 10) ? be1[tid] : be2[tid - 10];
            float sc = ga * rsqrtf(var + 1e-5f);
            g_scale[tid] = sc;
            g_shift[tid] = be - mean * sc;
        }
        __syncthreads();
        if (tid == 0) { g_arrive = 0u; __threadfence(); }   // reset for next replay
    }
}

// ===========================================================================
// Kernel 2: normalize + 30->64->32->1 ReLU MLP, one thread per row
// ===========================================================================
__global__ void __launch_bounds__(128)
k_mlp(const float* __restrict__ W1, const float* __restrict__ b1,
      const float* __restrict__ W2, const float* __restrict__ b2,
      const float* __restrict__ W3, const float* __restrict__ b3,
      float* __restrict__ out)
{
    __shared__ float sW1[64 * 30], sb1[64], sW2[32 * 64], sb2[32], sW3[32];
    __shared__ float ssc[20], ssh[20], sb3;
    const int tid = threadIdx.x;
    for (int i = tid; i < 64 * 30; i += 128) sW1[i] = W1[i];
    for (int i = tid; i < 32 * 64; i += 128) sW2[i] = W2[i];
    if (tid < 64) sb1[tid] = b1[tid];
    if (tid < 32) { sb2[tid] = b2[tid]; sW3[tid] = W3[tid]; }
    if (tid < 20) { ssc[tid] = g_scale[tid]; ssh[tid] = g_shift[tid]; }
    if (tid == 0) sb3 = b3[0];
    __syncthreads();

    const int r = blockIdx.x * 128 + tid;
    const float4* fp = (const float4*)(g_feat + (size_t)r * 32);
    float x[30];
    float4 v[8];
#pragma unroll
    for (int i = 0; i < 8; i++) v[i] = fp[i];
#pragma unroll
    for (int i = 0; i < 7; i++) {
        x[i * 4 + 0] = v[i].x; x[i * 4 + 1] = v[i].y;
        x[i * 4 + 2] = v[i].z; x[i * 4 + 3] = v[i].w;
    }
    x[28] = v[7].x; x[29] = v[7].y;

#pragma unroll
    for (int j = 0; j < 10; j++) {
        x[j]      = x[j]      * ssc[j]      + ssh[j];
        x[15 + j] = x[15 + j] * ssc[10 + j] + ssh[10 + j];
    }

    float h1[64];
#pragma unroll
    for (int o = 0; o < 64; o++) {
        float s = sb1[o];
#pragma unroll
        for (int i = 0; i < 30; i++) s += sW1[o * 30 + i] * x[i];
        h1[o] = fmaxf(s, 0.f);
    }
    float h2[32];
#pragma unroll
    for (int o = 0; o < 32; o++) {
        float s = sb2[o];
#pragma unroll
        for (int i = 0; i < 64; i++) s += sW2[o * 64 + i] * h1[i];
        h2[o] = fmaxf(s, 0.f);
    }
    float s = sb3;
#pragma unroll
    for (int i = 0; i < 32; i++) s += sW3[i] * h2[i];
    out[r] = fmaxf(s, 0.f);
}

// ===========================================================================
extern "C" void kernel_launch(void* const* d_in, const int* in_sizes, int n_in,
                              void* d_out, int out_size)
{
    (void)in_sizes; (void)n_in; (void)out_size;
    const float* user_feature = (const float*)d_in[2];
    const float* item_feature = (const float*)d_in[3];
    const float* user_tag     = (const float*)d_in[4];
    const float* item_tag     = (const float*)d_in[5];
    const float* W_user = (const float*)d_in[6];
    const float* b_user = (const float*)d_in[7];
    const float* W_item = (const float*)d_in[8];
    const float* b_item = (const float*)d_in[9];
    const float* E_user_tag = (const float*)d_in[10];
    const float* E_item_tag = (const float*)d_in[11];
    const float* g1  = (const float*)d_in[12];
    const float* be1 = (const float*)d_in[13];
    const float* g2  = (const float*)d_in[14];
    const float* be2 = (const float*)d_in[15];
    const float* W1 = (const float*)d_in[16];
    const float* b1 = (const float*)d_in[17];
    const float* W2 = (const float*)d_in[18];
    const float* b2 = (const float*)d_in[19];
    const float* W3 = (const float*)d_in[20];
    const float* b3 = (const float*)d_in[21];

    const int smem_bytes = (23040 + NWARP * 40) * (int)sizeof(float);  // 94,720 B
    cudaFuncSetAttribute(k_main, cudaFuncAttributeMaxDynamicSharedMemorySize, smem_bytes);

    k_main<<<GMAIN, 512, smem_bytes>>>(user_feature, item_feature, user_tag, item_tag,
                                       W_user, b_user, W_item, b_item,
                                       E_user_tag, E_item_tag,
                                       g1, be1, g2, be2);
    k_mlp<<<128, 128>>>(W1, b1, W2, b2, W3, b3, (float*)d_out);
}

// round 6
// speedup vs baseline: 1.1362x; 1.0189x over previous
#include <cuda_runtime.h>

// ---------------------------------------------------------------------------
// NCF_Feature: split structure.
//  k_main: bag (2x-unrolled) + GEMVs + one-hot (8-LDG chunks) + BN partials;
//          LAST block computes scale/shift.
//  k_mlp : warp-cooperative normalize + 30->64->32->1 ReLU MLP (low regs).
// ---------------------------------------------------------------------------

#define B_ROWS 16384
#define TAGS   4096
#define GMAIN  256            // blocks; 64 rows per block
#define NWARP  16             // warps per block (512 threads)

// Scratch (allocation-free rule: __device__ globals)
__device__ float g_feat[(size_t)B_ROWS * 32];   // [B][32]: u(10) eut(5) i(10) eit(5) pad
__device__ float g_part[GMAIN * 40];            // per-block: sum[20], sumsq[20]
__device__ float g_scale[20];
__device__ float g_shift[20];
__device__ unsigned int g_arrive;               // zero-init; self-resetting

__device__ __forceinline__ float warpsum(float v) {
#pragma unroll
    for (int o = 16; o; o >>= 1) v += __shfl_xor_sync(0xffffffffu, v, o);
    return v;
}

// ===========================================================================
// Kernel 1: HBM streamer. 512 threads, 2 CTA/SM. (unchanged from R5 best)
// ===========================================================================
__global__ void __launch_bounds__(512, 2)
k_main(const float* __restrict__ uf_g, const float* __restrict__ if_g,
       const float* __restrict__ ut_g, const float* __restrict__ it_g,
       const float* __restrict__ Wu,   const float* __restrict__ bu,
       const float* __restrict__ Wi,   const float* __restrict__ bi,
       const float* __restrict__ Eu,   const float* __restrict__ Ei,
       const float* __restrict__ g1,   const float* __restrict__ be1,
       const float* __restrict__ g2,   const float* __restrict__ be2)
{
    extern __shared__ float sm[];
    float* sE   = sm;                 // 5*4096 SoA
    float* sWu  = sm + 20480;         // 10*128
    float* sWi  = sm + 21760;         // 10*128
    float* sRed = sm + 23040;         // NWARP*40

    const int tid = threadIdx.x;

    for (int i = tid; i < TAGS; i += 512) {
        float e0 = Ei[i * 5 + 0], e1 = Ei[i * 5 + 1], e2 = Ei[i * 5 + 2];
        float e3 = Ei[i * 5 + 3], e4 = Ei[i * 5 + 4];
        sE[0 * TAGS + i] = e0; sE[1 * TAGS + i] = e1; sE[2 * TAGS + i] = e2;
        sE[3 * TAGS + i] = e3; sE[4 * TAGS + i] = e4;
    }
    for (int i = tid; i < 1280; i += 512) { sWu[i] = Wu[i]; sWi[i] = Wi[i]; }
    __syncthreads();

    const int warp = tid >> 5, lane = tid & 31;
    const int rowbase = blockIdx.x * 64 + warp * 4;
    const float4* sE4  = (const float4*)sE;
    const float4* sWu4 = (const float4*)sWu;
    const float4* sWi4 = (const float4*)sWi;

    float su = 0.f, sq = 0.f;

#pragma unroll 1
    for (int q = 0; q < 2; q++) {
        const int r0 = rowbase + q * 2;

        // ---- weighted tag bag: 2 rows, 2x unrolled -> 4 LDG.128 in flight ----
        const float4* t0 = (const float4*)(ut_g + (size_t)(r0 + 0) * TAGS);
        const float4* t1 = (const float4*)(ut_g + (size_t)(r0 + 1) * TAGS);
        float acc0[5], acc1[5];
#pragma unroll
        for (int k = 0; k < 5; k++) { acc0[k] = 0.f; acc1[k] = 0.f; }

#pragma unroll 1
        for (int i = lane; i < TAGS / 4; i += 64) {
            float4 a0 = t0[i];
            float4 a1 = t1[i];
            float4 b0 = t0[i + 32];
            float4 b1 = t1[i + 32];
            float4 ee;
#pragma unroll
            for (int k = 0; k < 5; k++) {
                ee = sE4[k * (TAGS / 4) + i];
                acc0[k] += a0.x * ee.x + a0.y * ee.y + a0.z * ee.z + a0.w * ee.w;
                acc1[k] += a1.x * ee.x + a1.y * ee.y + a1.z * ee.z + a1.w * ee.w;
            }
#pragma unroll
            for (int k = 0; k < 5; k++) {
                ee = sE4[k * (TAGS / 4) + i + 32];
                acc0[k] += b0.x * ee.x + b0.y * ee.y + b0.z * ee.z + b0.w * ee.w;
                acc1[k] += b1.x * ee.x + b1.y * ee.y + b1.z * ee.z + b1.w * ee.w;
            }
        }
#pragma unroll
        for (int k = 0; k < 5; k++) {
            float s0 = warpsum(acc0[k]) * 0.1f;
            float s1 = warpsum(acc1[k]) * 0.1f;
            if (lane == k) {
                g_feat[(size_t)(r0 + 0) * 32 + 10 + k] = s0;
                g_feat[(size_t)(r0 + 1) * 32 + 10 + k] = s1;
            }
        }

        // ---- per-row: GEMVs + one-hot search ----
#pragma unroll 1
        for (int r = 0; r < 2; r++) {
            const int rr = r0 + r;
            const float4* it4 = (const float4*)(it_g + (size_t)rr * TAGS);

            float4 v[8];
#pragma unroll
            for (int k = 0; k < 8; k++) v[k] = it4[k * 32 + lane];

            float4 xu = ((const float4*)(uf_g + (size_t)rr * 128))[lane];
            float4 xi = ((const float4*)(if_g + (size_t)rr * 128))[lane];
#pragma unroll
            for (int j = 0; j < 10; j++) {
                float4 wu = sWu4[j * 32 + lane];
                float s = warpsum(xu.x * wu.x + xu.y * wu.y + xu.z * wu.z + xu.w * wu.w) + bu[j];
                if (lane == j) { g_feat[(size_t)rr * 32 + j] = s; su += s; sq += s * s; }
                float4 wi = sWi4[j * 32 + lane];
                float s2 = warpsum(xi.x * wi.x + xi.y * wi.y + xi.z * wi.z + xi.w * wi.w) + bi[j];
                if (lane == j + 10) { g_feat[(size_t)rr * 32 + 15 + j] = s2; su += s2; sq += s2 * s2; }
            }

            int hot = 0;
#pragma unroll 1
            for (int base = 0; base < 1024; base += 256) {
                int m = 0;
#pragma unroll
                for (int k = 0; k < 8; k++) {
                    m |= (v[k].x == 1.f) << (k * 4 + 0);
                    m |= (v[k].y == 1.f) << (k * 4 + 1);
                    m |= (v[k].z == 1.f) << (k * 4 + 2);
                    m |= (v[k].w == 1.f) << (k * 4 + 3);
                }
                unsigned bal = __ballot_sync(0xffffffffu, m != 0);
                if (bal) {
                    int src = __ffs(bal) - 1;
                    int mm  = __shfl_sync(0xffffffffu, m, src);
                    int bit = __ffs(mm) - 1;
                    hot = 4 * (base + (bit >> 2) * 32 + src) + (bit & 3);
                    break;
                }
                if (base + 256 < 1024) {
#pragma unroll
                    for (int k = 0; k < 8; k++) v[k] = it4[base + 256 + k * 32 + lane];
                }
            }
            if (lane < 5) g_feat[(size_t)rr * 32 + 25 + lane] = Eu[(size_t)hot * 5 + lane];
        }
    }

    // ---- per-block BN partials -> g_part ----
    if (lane < 20) { sRed[warp * 40 + lane] = su; sRed[warp * 40 + 20 + lane] = sq; }
    __syncthreads();
    if (tid < 40) {
        float s = 0.f;
#pragma unroll
        for (int w = 0; w < NWARP; w++) s += sRed[w * 40 + tid];
        g_part[blockIdx.x * 40 + tid] = s;
    }

    // ---- last-arriving block computes BN scale/shift ----
    __threadfence();
    __syncthreads();
    __shared__ int sLast;
    if (tid == 0) sLast = (atomicAdd(&g_arrive, 1u) == GMAIN - 1);
    __syncthreads();
    if (sLast) {
        const int j = tid % 40, g = tid / 40;
        if (tid < 320) {
            float s = 0.f;
#pragma unroll 4
            for (int i = 0; i < 32; i++) s += g_part[(g * 32 + i) * 40 + j];
            sRed[g * 40 + j] = s;
        }
        __syncthreads();
        if (tid < 20) {
            float s0 = 0.f, s1 = 0.f;
#pragma unroll
            for (int gg = 0; gg < 8; gg++) { s0 += sRed[gg * 40 + tid]; s1 += sRed[gg * 40 + 20 + tid]; }
            float mean = s0 * (1.f / B_ROWS);
            float var  = s1 * (1.f / B_ROWS) - mean * mean;   // biased
            float ga = (tid < 10) ? g1[tid]  : g2[tid - 10];
            float be = (tid < 10) ? be1[tid] : be2[tid - 10];
            float sc = ga * rsqrtf(var + 1e-5f);
            g_scale[tid] = sc;
            g_shift[tid] = be - mean * sc;
        }
        __syncthreads();
        if (tid == 0) { g_arrive = 0u; __threadfence(); }
    }
}

// ===========================================================================
// Kernel 2: warp-cooperative normalize + MLP. One warp -> 8 rows.
//  layer1: 2 outputs/lane from smem x (broadcast); h1 -> smem (stride-padded)
//  layer2: 1 output/lane; layer3: warpsum.
// 128 blocks x 512 threads; ~40 regs -> high occupancy.
// ===========================================================================
__global__ void __launch_bounds__(512)
k_mlp(const float* __restrict__ W1, const float* __restrict__ b1,
      const float* __restrict__ W2, const float* __restrict__ b2,
      const float* __restrict__ W3, const float* __restrict__ b3,
      float* __restrict__ out)
{
    __shared__ float pW1[64 * 31];      // stride 31 (conflict-free)
    __shared__ float pW2[32 * 65];      // stride 65
    __shared__ float pb1[64], pb2[32], pW3[32];
    __shared__ float ssc[20], ssh[20];
    __shared__ float h1s[16][64];
    __shared__ float xbuf[16][32];
    __shared__ float sb3;

    const int tid = threadIdx.x;
    for (int i = tid; i < 1920; i += 512) pW1[(i / 30) * 31 + (i % 30)] = W1[i];
    for (int i = tid; i < 2048; i += 512) pW2[(i / 64) * 65 + (i % 64)] = W2[i];
    if (tid < 64) pb1[tid] = b1[tid];
    if (tid < 32) { pb2[tid] = b2[tid]; pW3[tid] = W3[tid]; }
    if (tid < 20) { ssc[tid] = g_scale[tid]; ssh[tid] = g_shift[tid]; }
    if (tid == 0) sb3 = b3[0];
    __syncthreads();

    const int warp = tid >> 5, lane = tid & 31;
    const int row0 = (blockIdx.x * 16 + warp) * 8;
    float* xw  = xbuf[warp];
    float* h1w = h1s[warp];
    const float b3v = sb3;

    // BN col mapping for lane<30: cols 0..9 -> stats 0..9; 15..24 -> 10..19
    const bool normed = (lane < 10) | (lane >= 15 && lane < 25);
    const int statj = (lane < 10) ? lane : lane - 5;
    const float scv = normed ? ssc[statj] : 1.f;
    const float shv = normed ? ssh[statj] : 0.f;

    const float* w1a = pW1 + lane * 31;
    const float* w1b = pW1 + (lane + 32) * 31;
    const float* w2l = pW2 + lane * 65;
    const float w3l = pW3[lane];
    const float b1a = pb1[lane], b1b = pb1[lane + 32], b2l = pb2[lane];

#pragma unroll 1
    for (int r = 0; r < 8; r++) {
        const int row = row0 + r;
        // load + normalize x (30 valid cols)
        if (lane < 30) xw[lane] = g_feat[(size_t)row * 32 + lane] * scv + shv;
        __syncwarp();

        float s0 = b1a, s1 = b1b;
#pragma unroll
        for (int i = 0; i < 30; i++) {
            float xv = xw[i];
            s0 += w1a[i] * xv;
            s1 += w1b[i] * xv;
        }
        __syncwarp();
        h1w[lane] = fmaxf(s0, 0.f);
        h1w[lane + 32] = fmaxf(s1, 0.f);
        __syncwarp();

        float s = b2l;
#pragma unroll
        for (int i = 0; i < 64; i++) s += w2l[i] * h1w[i];
        float h2 = fmaxf(s, 0.f);

        float v = warpsum(w3l * h2) + b3v;
        if (lane == 0) out[row] = fmaxf(v, 0.f);
        __syncwarp();
    }
}

// ===========================================================================
extern "C" void kernel_launch(void* const* d_in, const int* in_sizes, int n_in,
                              void* d_out, int out_size)
{
    (void)in_sizes; (void)n_in; (void)out_size;
    const float* user_feature = (const float*)d_in[2];
    const float* item_feature = (const float*)d_in[3];
    const float* user_tag     = (const float*)d_in[4];
    const float* item_tag     = (const float*)d_in[5];
    const float* W_user = (const float*)d_in[6];
    const float* b_user = (const float*)d_in[7];
    const float* W_item = (const float*)d_in[8];
    const float* b_item = (const float*)d_in[9];
    const float* E_user_tag = (const float*)d_in[10];
    const float* E_item_tag = (const float*)d_in[11];
    const float* g1  = (const float*)d_in[12];
    const float* be1 = (const float*)d_in[13];
    const float* g2  = (const float*)d_in[14];
    const float* be2 = (const float*)d_in[15];
    const float* W1 = (const float*)d_in[16];
    const float* b1 = (const float*)d_in[17];
    const float* W2 = (const float*)d_in[18];
    const float* b2 = (const float*)d_in[19];
    const float* W3 = (const float*)d_in[20];
    const float* b3 = (const float*)d_in[21];

    const int smem_bytes = (23040 + NWARP * 40) * (int)sizeof(float);  // 94,720 B
    cudaFuncSetAttribute(k_main, cudaFuncAttributeMaxDynamicSharedMemorySize, smem_bytes);

    k_main<<<GMAIN, 512, smem_bytes>>>(user_feature, item_feature, user_tag, item_tag,
                                       W_user, b_user, W_item, b_item,
                                       E_user_tag, E_item_tag,
                                       g1, be1, g2, be2);
    k_mlp<<<128, 512>>>(W1, b1, W2, b2, W3, b3, (float*)d_out);
}

// round 7
// speedup vs baseline: 1.1509x; 1.0130x over previous
#include <cuda_runtime.h>

// ---------------------------------------------------------------------------
// NCF_Feature: split structure.
//  k_main: bag (2x-unrolled) + GEMVs + one-hot (8-LDG chunks) + BN partials;
//          LAST block computes scale/shift. Feat written COLUMN-MAJOR.
//  k_mlp : lane-per-row fused 30->64->32->1 MLP (no h1 storage, LDS.128
//          broadcast weights, coalesced x loads).
// ---------------------------------------------------------------------------

#define B_ROWS 16384
#define TAGS   4096
#define GMAIN  256            // k_main blocks; 64 rows per block
#define NWARP  16             // warps per k_main block (512 threads)

// Scratch (allocation-free rule: __device__ globals)
__device__ float g_featT[32 * (size_t)B_ROWS];  // column-major: [col][row]
__device__ float g_part[GMAIN * 40];            // per-block: sum[20], sumsq[20]
__device__ float g_scale[20];
__device__ float g_shift[20];
__device__ unsigned int g_arrive;               // zero-init; self-resetting

__device__ __forceinline__ float warpsum(float v) {
#pragma unroll
    for (int o = 16; o; o >>= 1) v += __shfl_xor_sync(0xffffffffu, v, o);
    return v;
}

// ===========================================================================
// Kernel 1: HBM streamer. 512 threads, 2 CTA/SM.
// ===========================================================================
__global__ void __launch_bounds__(512, 2)
k_main(const float* __restrict__ uf_g, const float* __restrict__ if_g,
       const float* __restrict__ ut_g, const float* __restrict__ it_g,
       const float* __restrict__ Wu,   const float* __restrict__ bu,
       const float* __restrict__ Wi,   const float* __restrict__ bi,
       const float* __restrict__ Eu,   const float* __restrict__ Ei,
       const float* __restrict__ g1,   const float* __restrict__ be1,
       const float* __restrict__ g2,   const float* __restrict__ be2)
{
    extern __shared__ float sm[];
    float* sE   = sm;                 // 5*4096 SoA
    float* sWu  = sm + 20480;         // 10*128
    float* sWi  = sm + 21760;         // 10*128
    float* sRed = sm + 23040;         // NWARP*40

    const int tid = threadIdx.x;

    for (int i = tid; i < TAGS; i += 512) {
        float e0 = Ei[i * 5 + 0], e1 = Ei[i * 5 + 1], e2 = Ei[i * 5 + 2];
        float e3 = Ei[i * 5 + 3], e4 = Ei[i * 5 + 4];
        sE[0 * TAGS + i] = e0; sE[1 * TAGS + i] = e1; sE[2 * TAGS + i] = e2;
        sE[3 * TAGS + i] = e3; sE[4 * TAGS + i] = e4;
    }
    for (int i = tid; i < 1280; i += 512) { sWu[i] = Wu[i]; sWi[i] = Wi[i]; }
    __syncthreads();

    const int warp = tid >> 5, lane = tid & 31;
    const int rowbase = blockIdx.x * 64 + warp * 4;
    const float4* sE4  = (const float4*)sE;
    const float4* sWu4 = (const float4*)sWu;
    const float4* sWi4 = (const float4*)sWi;

    float su = 0.f, sq = 0.f;

#pragma unroll 1
    for (int q = 0; q < 2; q++) {
        const int r0 = rowbase + q * 2;

        // ---- weighted tag bag: 2 rows, 2x unrolled -> 4 LDG.128 in flight ----
        const float4* t0 = (const float4*)(ut_g + (size_t)(r0 + 0) * TAGS);
        const float4* t1 = (const float4*)(ut_g + (size_t)(r0 + 1) * TAGS);
        float acc0[5], acc1[5];
#pragma unroll
        for (int k = 0; k < 5; k++) { acc0[k] = 0.f; acc1[k] = 0.f; }

#pragma unroll 1
        for (int i = lane; i < TAGS / 4; i += 64) {
            float4 a0 = t0[i];
            float4 a1 = t1[i];
            float4 b0 = t0[i + 32];
            float4 b1 = t1[i + 32];
            float4 ee;
#pragma unroll
            for (int k = 0; k < 5; k++) {
                ee = sE4[k * (TAGS / 4) + i];
                acc0[k] += a0.x * ee.x + a0.y * ee.y + a0.z * ee.z + a0.w * ee.w;
                acc1[k] += a1.x * ee.x + a1.y * ee.y + a1.z * ee.z + a1.w * ee.w;
            }
#pragma unroll
            for (int k = 0; k < 5; k++) {
                ee = sE4[k * (TAGS / 4) + i + 32];
                acc0[k] += b0.x * ee.x + b0.y * ee.y + b0.z * ee.z + b0.w * ee.w;
                acc1[k] += b1.x * ee.x + b1.y * ee.y + b1.z * ee.z + b1.w * ee.w;
            }
        }
#pragma unroll
        for (int k = 0; k < 5; k++) {
            float s0 = warpsum(acc0[k]) * 0.1f;
            float s1 = warpsum(acc1[k]) * 0.1f;
            if (lane == k) {
                g_featT[(10 + k) * (size_t)B_ROWS + (r0 + 0)] = s0;
                g_featT[(10 + k) * (size_t)B_ROWS + (r0 + 1)] = s1;
            }
        }

        // ---- per-row: GEMVs + one-hot search ----
#pragma unroll 1
        for (int r = 0; r < 2; r++) {
            const int rr = r0 + r;
            const float4* it4 = (const float4*)(it_g + (size_t)rr * TAGS);

            float4 v[8];
#pragma unroll
            for (int k = 0; k < 8; k++) v[k] = it4[k * 32 + lane];

            float4 xu = ((const float4*)(uf_g + (size_t)rr * 128))[lane];
            float4 xi = ((const float4*)(if_g + (size_t)rr * 128))[lane];
#pragma unroll
            for (int j = 0; j < 10; j++) {
                float4 wu = sWu4[j * 32 + lane];
                float s = warpsum(xu.x * wu.x + xu.y * wu.y + xu.z * wu.z + xu.w * wu.w) + bu[j];
                if (lane == j) { g_featT[j * (size_t)B_ROWS + rr] = s; su += s; sq += s * s; }
                float4 wi = sWi4[j * 32 + lane];
                float s2 = warpsum(xi.x * wi.x + xi.y * wi.y + xi.z * wi.z + xi.w * wi.w) + bi[j];
                if (lane == j + 10) { g_featT[(15 + j) * (size_t)B_ROWS + rr] = s2; su += s2; sq += s2 * s2; }
            }

            int hot = 0;
#pragma unroll 1
            for (int base = 0; base < 1024; base += 256) {
                int m = 0;
#pragma unroll
                for (int k = 0; k < 8; k++) {
                    m |= (v[k].x == 1.f) << (k * 4 + 0);
                    m |= (v[k].y == 1.f) << (k * 4 + 1);
                    m |= (v[k].z == 1.f) << (k * 4 + 2);
                    m |= (v[k].w == 1.f) << (k * 4 + 3);
                }
                unsigned bal = __ballot_sync(0xffffffffu, m != 0);
                if (bal) {
                    int src = __ffs(bal) - 1;
                    int mm  = __shfl_sync(0xffffffffu, m, src);
                    int bit = __ffs(mm) - 1;
                    hot = 4 * (base + (bit >> 2) * 32 + src) + (bit & 3);
                    break;
                }
                if (base + 256 < 1024) {
#pragma unroll
                    for (int k = 0; k < 8; k++) v[k] = it4[base + 256 + k * 32 + lane];
                }
            }
            if (lane < 5) g_featT[(25 + lane) * (size_t)B_ROWS + rr] = Eu[(size_t)hot * 5 + lane];
        }
    }

    // ---- per-block BN partials -> g_part ----
    if (lane < 20) { sRed[warp * 40 + lane] = su; sRed[warp * 40 + 20 + lane] = sq; }
    __syncthreads();
    if (tid < 40) {
        float s = 0.f;
#pragma unroll
        for (int w = 0; w < NWARP; w++) s += sRed[w * 40 + tid];
        g_part[blockIdx.x * 40 + tid] = s;
    }

    // ---- last-arriving block computes BN scale/shift ----
    __threadfence();
    __syncthreads();
    __shared__ int sLast;
    if (tid == 0) sLast = (atomicAdd(&g_arrive, 1u) == GMAIN - 1);
    __syncthreads();
    if (sLast) {
        const int j = tid % 40, g = tid / 40;
        if (tid < 320) {
            float s = 0.f;
#pragma unroll 4
            for (int i = 0; i < 32; i++) s += g_part[(g * 32 + i) * 40 + j];
            sRed[g * 40 + j] = s;
        }
        __syncthreads();
        if (tid < 20) {
            float s0 = 0.f, s1 = 0.f;
#pragma unroll
            for (int gg = 0; gg < 8; gg++) { s0 += sRed[gg * 40 + tid]; s1 += sRed[gg * 40 + 20 + tid]; }
            float mean = s0 * (1.f / B_ROWS);
            float var  = s1 * (1.f / B_ROWS) - mean * mean;   // biased
            float ga = (tid < 10) ? g1[tid]  : g2[tid - 10];
            float be = (tid < 10) ? be1[tid] : be2[tid - 10];
            float sc = ga * rsqrtf(var + 1e-5f);
            g_scale[tid] = sc;
            g_shift[tid] = be - mean * sc;
        }
        __syncthreads();
        if (tid == 0) { g_arrive = 0u; __threadfence(); }
    }
}

// ===========================================================================
// Kernel 2: lane-per-row fused MLP. One lane = one row; h1 never stored.
//  h2[32] in regs; weights via LDS.128 broadcast (W1 stride-32, W2 transposed).
//  128 blocks x 128 threads = 512 warps x 32 rows.
// ===========================================================================
__global__ void __launch_bounds__(128)
k_mlp(const float* __restrict__ W1, const float* __restrict__ b1,
      const float* __restrict__ W2, const float* __restrict__ b2,
      const float* __restrict__ W3, const float* __restrict__ b3,
      float* __restrict__ out)
{
    __shared__ float sW1[64 * 32];      // [o][i], i padded 30->32 with zeros
    __shared__ float sW2T[64 * 32];     // [o][j] (transposed W2)
    __shared__ float sb1[64];
    __shared__ float sb2[32];
    __shared__ float sW3[32];
    __shared__ float csc[32], csh[32];  // per-feature-column scale/shift
    __shared__ float sb3;

    const int tid = threadIdx.x;
    // zero pads first, then fill (sync between: different threads touch both)
    for (int i = tid; i < 64 * 32; i += 128) { sW1[i] = 0.f; }
    __syncthreads();
    for (int i = tid; i < 1920; i += 128) sW1[(i / 30) * 32 + (i % 30)] = W1[i];
    for (int i = tid; i < 2048; i += 128) sW2T[(i % 64) * 32 + (i / 64)] = W2[i];
    if (tid < 64) sb1[tid] = b1[tid];
    if (tid < 32) { sb2[tid] = b2[tid]; sW3[tid] = W3[tid]; }
    if (tid < 32) {
        // col c: 0..9 -> stat c; 15..24 -> stat c-5; else identity
        int c = tid;
        bool bn = (c < 10) || (c >= 15 && c < 25);
        int sj = (c < 10) ? c : c - 5;
        csc[c] = bn ? g_scale[sj] : 1.f;
        csh[c] = bn ? g_shift[sj] : 0.f;
    }
    if (tid == 0) sb3 = b3[0];
    __syncthreads();

    const int warp = tid >> 5, lane = tid & 31;
    const int row = (blockIdx.x * 4 + warp) * 32 + lane;

    // load + normalize x (coalesced: column-major feat)
    float x[32];
#pragma unroll
    for (int i = 0; i < 30; i++)
        x[i] = g_featT[i * (size_t)B_ROWS + row] * csc[i] + csh[i];
    x[30] = 0.f; x[31] = 0.f;

    float h2[32];
#pragma unroll
    for (int j = 0; j < 32; j++) h2[j] = sb2[j];

    const float4* w1v = (const float4*)sW1;
    const float4* w2v = (const float4*)sW2T;

#pragma unroll 4
    for (int o = 0; o < 64; o++) {
        float t = sb1[o];
#pragma unroll
        for (int i4 = 0; i4 < 8; i4++) {
            float4 w = w1v[o * 8 + i4];
            t += w.x * x[i4 * 4 + 0] + w.y * x[i4 * 4 + 1]
               + w.z * x[i4 * 4 + 2] + w.w * x[i4 * 4 + 3];
        }
        t = fmaxf(t, 0.f);
#pragma unroll
        for (int j4 = 0; j4 < 8; j4++) {
            float4 w = w2v[o * 8 + j4];
            h2[j4 * 4 + 0] += w.x * t;
            h2[j4 * 4 + 1] += w.y * t;
            h2[j4 * 4 + 2] += w.z * t;
            h2[j4 * 4 + 3] += w.w * t;
        }
    }

    float s = sb3;
    const float4* w3v = (const float4*)sW3;
#pragma unroll
    for (int j4 = 0; j4 < 8; j4++) {
        float4 w = w3v[j4];
        s += w.x * fmaxf(h2[j4 * 4 + 0], 0.f)
           + w.y * fmaxf(h2[j4 * 4 + 1], 0.f)
           + w.z * fmaxf(h2[j4 * 4 + 2], 0.f)
           + w.w * fmaxf(h2[j4 * 4 + 3], 0.f);
    }
    out[row] = fmaxf(s, 0.f);
}

// ===========================================================================
extern "C" void kernel_launch(void* const* d_in, const int* in_sizes, int n_in,
                              void* d_out, int out_size)
{
    (void)in_sizes; (void)n_in; (void)out_size;
    const float* user_feature = (const float*)d_in[2];
    const float* item_feature = (const float*)d_in[3];
    const float* user_tag     = (const float*)d_in[4];
    const float* item_tag     = (const float*)d_in[5];
    const float* W_user = (const float*)d_in[6];
    const float* b_user = (const float*)d_in[7];
    const float* W_item = (const float*)d_in[8];
    const float* b_item = (const float*)d_in[9];
    const float* E_user_tag = (const float*)d_in[10];
    const float* E_item_tag = (const float*)d_in[11];
    const float* g1  = (const float*)d_in[12];
    const float* be1 = (const float*)d_in[13];
    const float* g2  = (const float*)d_in[14];
    const float* be2 = (const float*)d_in[15];
    const float* W1 = (const float*)d_in[16];
    const float* b1 = (const float*)d_in[17];
    const float* W2 = (const float*)d_in[18];
    const float* b2 = (const float*)d_in[19];
    const float* W3 = (const float*)d_in[20];
    const float* b3 = (const float*)d_in[21];

    const int smem_bytes = (23040 + NWARP * 40) * (int)sizeof(float);  // 94,720 B
    cudaFuncSetAttribute(k_main, cudaFuncAttributeMaxDynamicSharedMemorySize, smem_bytes);

    k_main<<<GMAIN, 512, smem_bytes>>>(user_feature, item_feature, user_tag, item_tag,
                                       W_user, b_user, W_item, b_item,
                                       E_user_tag, E_item_tag,
                                       g1, be1, g2, be2);
    k_mlp<<<128, 128>>>(W1, b1, W2, b2, W3, b3, (float*)d_out);
}

// round 8
// speedup vs baseline: 1.1964x; 1.0395x over previous
#include <cuda_runtime.h>

// ---------------------------------------------------------------------------
// NCF_Feature: split structure.
//  k_main: bag (2x-unrolled) + GEMVs + one-hot (8-LDG chunks) + BN partials;
//          LAST block computes scale/shift. Feat written COLUMN-MAJOR.
//  k_mlp : 4 sub-lanes per row; o-loop split; h2 reduced via shfl_xor.
// ---------------------------------------------------------------------------

#define B_ROWS 16384
#define TAGS   4096
#define GMAIN  256            // k_main blocks; 64 rows per block
#define NWARP  16             // warps per k_main block (512 threads)

// Scratch (allocation-free rule: __device__ globals)
__device__ float g_featT[32 * (size_t)B_ROWS];  // column-major: [col][row]
__device__ float g_part[GMAIN * 40];            // per-block: sum[20], sumsq[20]
__device__ float g_scale[20];
__device__ float g_shift[20];
__device__ unsigned int g_arrive;               // zero-init; self-resetting

__device__ __forceinline__ float warpsum(float v) {
#pragma unroll
    for (int o = 16; o; o >>= 1) v += __shfl_xor_sync(0xffffffffu, v, o);
    return v;
}

// ===========================================================================
// Kernel 1: HBM streamer. 512 threads, 2 CTA/SM. (unchanged from R7 best)
// ===========================================================================
__global__ void __launch_bounds__(512, 2)
k_main(const float* __restrict__ uf_g, const float* __restrict__ if_g,
       const float* __restrict__ ut_g, const float* __restrict__ it_g,
       const float* __restrict__ Wu,   const float* __restrict__ bu,
       const float* __restrict__ Wi,   const float* __restrict__ bi,
       const float* __restrict__ Eu,   const float* __restrict__ Ei,
       const float* __restrict__ g1,   const float* __restrict__ be1,
       const float* __restrict__ g2,   const float* __restrict__ be2)
{
    extern __shared__ float sm[];
    float* sE   = sm;                 // 5*4096 SoA
    float* sWu  = sm + 20480;         // 10*128
    float* sWi  = sm + 21760;         // 10*128
    float* sRed = sm + 23040;         // NWARP*40

    const int tid = threadIdx.x;

    for (int i = tid; i < TAGS; i += 512) {
        float e0 = Ei[i * 5 + 0], e1 = Ei[i * 5 + 1], e2 = Ei[i * 5 + 2];
        float e3 = Ei[i * 5 + 3], e4 = Ei[i * 5 + 4];
        sE[0 * TAGS + i] = e0; sE[1 * TAGS + i] = e1; sE[2 * TAGS + i] = e2;
        sE[3 * TAGS + i] = e3; sE[4 * TAGS + i] = e4;
    }
    for (int i = tid; i < 1280; i += 512) { sWu[i] = Wu[i]; sWi[i] = Wi[i]; }
    __syncthreads();

    const int warp = tid >> 5, lane = tid & 31;
    const int rowbase = blockIdx.x * 64 + warp * 4;
    const float4* sE4  = (const float4*)sE;
    const float4* sWu4 = (const float4*)sWu;
    const float4* sWi4 = (const float4*)sWi;

    float su = 0.f, sq = 0.f;

#pragma unroll 1
    for (int q = 0; q < 2; q++) {
        const int r0 = rowbase + q * 2;

        // ---- weighted tag bag: 2 rows, 2x unrolled -> 4 LDG.128 in flight ----
        const float4* t0 = (const float4*)(ut_g + (size_t)(r0 + 0) * TAGS);
        const float4* t1 = (const float4*)(ut_g + (size_t)(r0 + 1) * TAGS);
        float acc0[5], acc1[5];
#pragma unroll
        for (int k = 0; k < 5; k++) { acc0[k] = 0.f; acc1[k] = 0.f; }

#pragma unroll 1
        for (int i = lane; i < TAGS / 4; i += 64) {
            float4 a0 = t0[i];
            float4 a1 = t1[i];
            float4 b0 = t0[i + 32];
            float4 b1 = t1[i + 32];
            float4 ee;
#pragma unroll
            for (int k = 0; k < 5; k++) {
                ee = sE4[k * (TAGS / 4) + i];
                acc0[k] += a0.x * ee.x + a0.y * ee.y + a0.z * ee.z + a0.w * ee.w;
                acc1[k] += a1.x * ee.x + a1.y * ee.y + a1.z * ee.z + a1.w * ee.w;
            }
#pragma unroll
            for (int k = 0; k < 5; k++) {
                ee = sE4[k * (TAGS / 4) + i + 32];
                acc0[k] += b0.x * ee.x + b0.y * ee.y + b0.z * ee.z + b0.w * ee.w;
                acc1[k] += b1.x * ee.x + b1.y * ee.y + b1.z * ee.z + b1.w * ee.w;
            }
        }
#pragma unroll
        for (int k = 0; k < 5; k++) {
            float s0 = warpsum(acc0[k]) * 0.1f;
            float s1 = warpsum(acc1[k]) * 0.1f;
            if (lane == k) {
                g_featT[(10 + k) * (size_t)B_ROWS + (r0 + 0)] = s0;
                g_featT[(10 + k) * (size_t)B_ROWS + (r0 + 1)] = s1;
            }
        }

        // ---- per-row: GEMVs + one-hot search ----
#pragma unroll 1
        for (int r = 0; r < 2; r++) {
            const int rr = r0 + r;
            const float4* it4 = (const float4*)(it_g + (size_t)rr * TAGS);

            float4 v[8];
#pragma unroll
            for (int k = 0; k < 8; k++) v[k] = it4[k * 32 + lane];

            float4 xu = ((const float4*)(uf_g + (size_t)rr * 128))[lane];
            float4 xi = ((const float4*)(if_g + (size_t)rr * 128))[lane];
#pragma unroll
            for (int j = 0; j < 10; j++) {
                float4 wu = sWu4[j * 32 + lane];
                float s = warpsum(xu.x * wu.x + xu.y * wu.y + xu.z * wu.z + xu.w * wu.w) + bu[j];
                if (lane == j) { g_featT[j * (size_t)B_ROWS + rr] = s; su += s; sq += s * s; }
                float4 wi = sWi4[j * 32 + lane];
                float s2 = warpsum(xi.x * wi.x + xi.y * wi.y + xi.z * wi.z + xi.w * wi.w) + bi[j];
                if (lane == j + 10) { g_featT[(15 + j) * (size_t)B_ROWS + rr] = s2; su += s2; sq += s2 * s2; }
            }

            int hot = 0;
#pragma unroll 1
            for (int base = 0; base < 1024; base += 256) {
                int m = 0;
#pragma unroll
                for (int k = 0; k < 8; k++) {
                    m |= (v[k].x == 1.f) << (k * 4 + 0);
                    m |= (v[k].y == 1.f) << (k * 4 + 1);
                    m |= (v[k].z == 1.f) << (k * 4 + 2);
                    m |= (v[k].w == 1.f) << (k * 4 + 3);
                }
                unsigned bal = __ballot_sync(0xffffffffu, m != 0);
                if (bal) {
                    int src = __ffs(bal) - 1;
                    int mm  = __shfl_sync(0xffffffffu, m, src);
                    int bit = __ffs(mm) - 1;
                    hot = 4 * (base + (bit >> 2) * 32 + src) + (bit & 3);
                    break;
                }
                if (base + 256 < 1024) {
#pragma unroll
                    for (int k = 0; k < 8; k++) v[k] = it4[base + 256 + k * 32 + lane];
                }
            }
            if (lane < 5) g_featT[(25 + lane) * (size_t)B_ROWS + rr] = Eu[(size_t)hot * 5 + lane];
        }
    }

    // ---- per-block BN partials -> g_part ----
    if (lane < 20) { sRed[warp * 40 + lane] = su; sRed[warp * 40 + 20 + lane] = sq; }
    __syncthreads();
    if (tid < 40) {
        float s = 0.f;
#pragma unroll
        for (int w = 0; w < NWARP; w++) s += sRed[w * 40 + tid];
        g_part[blockIdx.x * 40 + tid] = s;
    }

    // ---- last-arriving block computes BN scale/shift ----
    __threadfence();
    __syncthreads();
    __shared__ int sLast;
    if (tid == 0) sLast = (atomicAdd(&g_arrive, 1u) == GMAIN - 1);
    __syncthreads();
    if (sLast) {
        const int j = tid % 40, g = tid / 40;
        if (tid < 320) {
            float s = 0.f;
#pragma unroll 4
            for (int i = 0; i < 32; i++) s += g_part[(g * 32 + i) * 40 + j];
            sRed[g * 40 + j] = s;
        }
        __syncthreads();
        if (tid < 20) {
            float s0 = 0.f, s1 = 0.f;
#pragma unroll
            for (int gg = 0; gg < 8; gg++) { s0 += sRed[gg * 40 + tid]; s1 += sRed[gg * 40 + 20 + tid]; }
            float mean = s0 * (1.f / B_ROWS);
            float var  = s1 * (1.f / B_ROWS) - mean * mean;   // biased
            float ga = (tid < 10) ? g1[tid]  : g2[tid - 10];
            float be = (tid < 10) ? be1[tid] : be2[tid - 10];
            float sc = ga * rsqrtf(var + 1e-5f);
            g_scale[tid] = sc;
            g_shift[tid] = be - mean * sc;
        }
        __syncthreads();
        if (tid == 0) { g_arrive = 0u; __threadfence(); }
    }
}

// ===========================================================================
// Kernel 2: 4 sub-lanes per row. Warp = 8 rows x 4 subs; sub s computes h1
// outputs [16s,16s+16) and partial h2[32]; shfl_xor(8,16) reduces h2; all
// lanes do layer 3; sub 0 writes. 128 blocks x 512 threads = 2048 warps.
// ===========================================================================
__global__ void __launch_bounds__(512)
k_mlp(const float* __restrict__ W1, const float* __restrict__ b1,
      const float* __restrict__ W2, const float* __restrict__ b2,
      const float* __restrict__ W3, const float* __restrict__ b3,
      float* __restrict__ out)
{
    __shared__ float sW1[64 * 32];      // [o][i], i padded 30->32 with zeros
    __shared__ float sW2T[64 * 32];     // [o][j] (transposed W2)
    __shared__ float sb1[64];
    __shared__ float sb2[32];
    __shared__ float sW3[32];
    __shared__ float csc[32], csh[32];
    __shared__ float sb3;

    const int tid = threadIdx.x;
    for (int i = tid; i < 64 * 32; i += 512) sW1[i] = 0.f;
    __syncthreads();
    for (int i = tid; i < 1920; i += 512) sW1[(i / 30) * 32 + (i % 30)] = W1[i];
    for (int i = tid; i < 2048; i += 512) sW2T[(i % 64) * 32 + (i / 64)] = W2[i];
    if (tid < 64) sb1[tid] = b1[tid];
    if (tid < 32) { sb2[tid] = b2[tid]; sW3[tid] = W3[tid]; }
    if (tid < 32) {
        int c = tid;
        bool bn = (c < 10) || (c >= 15 && c < 25);
        int sj = (c < 10) ? c : c - 5;
        csc[c] = bn ? g_scale[sj] : 1.f;
        csh[c] = bn ? g_shift[sj] : 0.f;
    }
    if (tid == 0) sb3 = b3[0];
    __syncthreads();

    const int warp = tid >> 5, lane = tid & 31;
    const int sub = lane >> 3, r = lane & 7;
    const int row = blockIdx.x * 128 + warp * 8 + r;

    // load + normalize x (8 distinct rows per warp; subs broadcast via L1)
    float x[32];
#pragma unroll
    for (int i = 0; i < 30; i++)
        x[i] = g_featT[i * (size_t)B_ROWS + row] * csc[i] + csh[i];
    x[30] = 0.f; x[31] = 0.f;

    float h2[32];
#pragma unroll
    for (int j = 0; j < 32; j++) h2[j] = (sub == 0) ? sb2[j] : 0.f;

    const float4* w1v = (const float4*)sW1;
    const float4* w2v = (const float4*)sW2T;
    const int ob = sub * 16;

#pragma unroll 4
    for (int oo = 0; oo < 16; oo++) {
        const int o = ob + oo;
        float t = sb1[o];
#pragma unroll
        for (int i4 = 0; i4 < 8; i4++) {
            float4 w = w1v[o * 8 + i4];
            t += w.x * x[i4 * 4 + 0] + w.y * x[i4 * 4 + 1]
               + w.z * x[i4 * 4 + 2] + w.w * x[i4 * 4 + 3];
        }
        t = fmaxf(t, 0.f);
#pragma unroll
        for (int j4 = 0; j4 < 8; j4++) {
            float4 w = w2v[o * 8 + j4];
            h2[j4 * 4 + 0] += w.x * t;
            h2[j4 * 4 + 1] += w.y * t;
            h2[j4 * 4 + 2] += w.z * t;
            h2[j4 * 4 + 3] += w.w * t;
        }
    }

    // reduce partial h2 across the 4 subs of this row
#pragma unroll
    for (int j = 0; j < 32; j++) {
        h2[j] += __shfl_xor_sync(0xffffffffu, h2[j], 8);
        h2[j] += __shfl_xor_sync(0xffffffffu, h2[j], 16);
    }

    float s = sb3;
    const float4* w3v = (const float4*)sW3;
#pragma unroll
    for (int j4 = 0; j4 < 8; j4++) {
        float4 w = w3v[j4];
        s += w.x * fmaxf(h2[j4 * 4 + 0], 0.f)
           + w.y * fmaxf(h2[j4 * 4 + 1], 0.f)
           + w.z * fmaxf(h2[j4 * 4 + 2], 0.f)
           + w.w * fmaxf(h2[j4 * 4 + 3], 0.f);
    }
    if (sub == 0) out[row] = fmaxf(s, 0.f);
}

// ===========================================================================
extern "C" void kernel_launch(void* const* d_in, const int* in_sizes, int n_in,
                              void* d_out, int out_size)
{
    (void)in_sizes; (void)n_in; (void)out_size;
    const float* user_feature = (const float*)d_in[2];
    const float* item_feature = (const float*)d_in[3];
    const float* user_tag     = (const float*)d_in[4];
    const float* item_tag     = (const float*)d_in[5];
    const float* W_user = (const float*)d_in[6];
    const float* b_user = (const float*)d_in[7];
    const float* W_item = (const float*)d_in[8];
    const float* b_item = (const float*)d_in[9];
    const float* E_user_tag = (const float*)d_in[10];
    const float* E_item_tag = (const float*)d_in[11];
    const float* g1  = (const float*)d_in[12];
    const float* be1 = (const float*)d_in[13];
    const float* g2  = (const float*)d_in[14];
    const float* be2 = (const float*)d_in[15];
    const float* W1 = (const float*)d_in[16];
    const float* b1 = (const float*)d_in[17];
    const float* W2 = (const float*)d_in[18];
    const float* b2 = (const float*)d_in[19];
    const float* W3 = (const float*)d_in[20];
    const float* b3 = (const float*)d_in[21];

    const int smem_bytes = (23040 + NWARP * 40) * (int)sizeof(float);  // 94,720 B
    cudaFuncSetAttribute(k_main, cudaFuncAttributeMaxDynamicSharedMemorySize, smem_bytes);

    k_main<<<GMAIN, 512, smem_bytes>>>(user_feature, item_feature, user_tag, item_tag,
                                       W_user, b_user, W_item, b_item,
                                       E_user_tag, E_item_tag,
                                       g1, be1, g2, be2);
    k_mlp<<<128, 512>>>(W1, b1, W2, b2, W3, b3, (float*)d_out);
}